// round 1
// baseline (speedup 1.0000x reference)
#include <cuda_runtime.h>

#define Bn 16
#define Nn 1024
#define Dn 8
#define Cn 128
#define Hn 256
#define NCOND 3
#define MAXIT 4

// ---------------- device scratch (no allocations allowed) ----------------
__device__ __align__(16) float g_x0[Bn * Nn * Dn];      // 512 KB
__device__ float g_cc[Bn * Hn];
__device__ unsigned char g_mask[Bn * Nn];
__device__ int g_count;
__device__ int g_active;
__device__ float g_partial[128];

// ---------------- init: x0 = where(cond, data, x0_noise); count=0 --------
__global__ void k_init(const float* __restrict__ data,
                       const float* __restrict__ x0_noise) {
    int i = blockIdx.x * blockDim.x + threadIdx.x;
    if (i == 0) g_count = 0;
    if (i < Bn * Nn * Dn) {
        int d = i & (Dn - 1);
        g_x0[i] = (d < NCOND) ? data[i] : x0_noise[i];
    }
}

// ---------------- cc = c @ Wc  (B x H) -----------------------------------
__global__ void k_cc(const float* __restrict__ c, const float* __restrict__ Wc) {
    int b = blockIdx.x;
    int h = threadIdx.x;
    float acc = 0.f;
    #pragma unroll 8
    for (int j = 0; j < Cn; j++)
        acc = fmaf(c[b * Cn + j], Wc[j * Hn + h], acc);
    g_cc[b * Hn + h] = acc;
}

// ---------------- mismatch: mask[b,n] = (argmin_m ||x_n - data_m||^2 != n)
// grid = B*32 blocks, 128 threads; 32 rows/block, 4-way m-split per row.
__global__ void k_mismatch(const float* __restrict__ data, int gated) {
    if (gated && g_active == 0) return;

    __shared__ float4 sdata[Nn * 2];   // 32 KB: data[b], 2 float4 per row
    __shared__ int sflag[32];

    const int tid  = threadIdx.x;
    const int b    = blockIdx.x >> 5;
    const int tile = blockIdx.x & 31;
    const int q    = tid & 3;          // m-quarter
    const int r    = tid >> 2;         // row within tile
    const int row  = tile * 32 + r;    // row within batch b

    const float4* dptr = (const float4*)(data + (size_t)b * Nn * Dn);
    for (int i = tid; i < Nn * 2; i += 128) sdata[i] = dptr[i];
    __syncthreads();

    const float4* xr = (const float4*)(g_x0 + ((size_t)b * Nn + row) * Dn);
    const float4 xa = xr[0];
    const float4 xb = xr[1];

    float best = 3.402823466e38f;
    int bidx = -1;
    const int m0 = q * 256;
    #pragma unroll 4
    for (int m = m0; m < m0 + 256; m++) {
        float4 da = sdata[2 * m];
        float4 db = sdata[2 * m + 1];
        // sequential accumulation d = 0..7 (matches reference reduction order)
        float t0 = xa.x - da.x; float acc = t0 * t0;
        t0 = xa.y - da.y; acc = fmaf(t0, t0, acc);
        t0 = xa.z - da.z; acc = fmaf(t0, t0, acc);
        t0 = xa.w - da.w; acc = fmaf(t0, t0, acc);
        t0 = xb.x - db.x; acc = fmaf(t0, t0, acc);
        t0 = xb.y - db.y; acc = fmaf(t0, t0, acc);
        t0 = xb.z - db.z; acc = fmaf(t0, t0, acc);
        t0 = xb.w - db.w; acc = fmaf(t0, t0, acc);
        if (acc < best) { best = acc; bidx = m; }   // strict < -> first index
    }

    // merge the 4 m-quarters (lanes 4r..4r+3); tie -> lower m (first index)
    #pragma unroll
    for (int off = 2; off >= 1; off >>= 1) {
        float ob = __shfl_down_sync(0xffffffffu, best, off, 4);
        int   oi = __shfl_down_sync(0xffffffffu, bidx, off, 4);
        if (ob < best || (ob == best && oi < bidx)) { best = ob; bidx = oi; }
    }

    if (q == 0) {
        int mm = (bidx != row) ? 1 : 0;
        g_mask[b * Nn + row] = (unsigned char)mm;
        sflag[r] = mm;
    }
    __syncthreads();
    if (tid == 0) {
        int s = 0;
        #pragma unroll
        for (int i = 0; i < 32; i++) s += sflag[i];
        if (s) atomicAdd(&g_count, s);
    }
}

// ---------------- gate: decide whether the while-body runs this iteration
__global__ void k_gate() {
    if (g_count >= 10) { g_active = 1; g_count = 0; }
    else               { g_active = 0; }
}

// ---------------- body replacement: masked rows get fresh noise (free dims)
__global__ void k_replace(const float* __restrict__ noise_bank, int iter) {
    if (g_active == 0) return;
    int i = blockIdx.x * blockDim.x + threadIdx.x;   // (b,n) flat
    if (i >= Bn * Nn) return;
    if (g_mask[i]) {
        const float* nb = noise_bank + (size_t)iter * Bn * Nn * Dn + (size_t)i * Dn;
        float* x = g_x0 + (size_t)i * Dn;
        #pragma unroll
        for (int d = NCOND; d < Dn; d++) x[d] = nb[d];
    }
}

// ---------------- fused model + masked squared-error partial sums ---------
// grid = 128 blocks (b*8 + tile), 128 threads, one row per thread.
__global__ void k_final(const float* __restrict__ data, const float* __restrict__ t,
                        const float* __restrict__ W1, const float* __restrict__ Wt,
                        const float* __restrict__ b1, const float* __restrict__ W2) {
    __shared__ float sW1[Dn * Hn];   // 8 KB  (D,H) row-major
    __shared__ float sW2[Hn * Dn];   // 8 KB  (H,D) row-major
    __shared__ float sbase[Hn];
    __shared__ float sred[128];

    const int bid  = blockIdx.x;
    const int b    = bid >> 3;
    const int tile = bid & 7;
    const int tid  = threadIdx.x;

    for (int i = tid; i < Dn * Hn; i += 128) sW1[i] = W1[i];
    for (int i = tid; i < Hn * Dn; i += 128) sW2[i] = W2[i];
    const float tb = t[b];
    for (int h = tid; h < Hn; h += 128)
        sbase[h] = g_cc[b * Hn + h] + tb * Wt[h] + b1[h];
    __syncthreads();

    const int row  = tile * 128 + tid;
    const int base = (b * Nn + row) * Dn;

    float xt[Dn], ut[Dn], vt[Dn];
    #pragma unroll
    for (int d = 0; d < Dn; d++) {
        float dv = data[base + d];
        float xv = g_x0[base + d];
        ut[d] = dv - xv;
        xt[d] = (d < NCOND) ? dv : ((1.0f - tb) * xv + tb * dv);
        vt[d] = 0.f;
    }

    for (int h = 0; h < Hn; h++) {
        float pre = sbase[h];
        #pragma unroll
        for (int d = 0; d < Dn; d++) pre = fmaf(xt[d], sW1[d * Hn + h], pre);
        float hh = tanhf(pre);
        #pragma unroll
        for (int d = 0; d < Dn; d++) vt[d] = fmaf(hh, sW2[h * Dn + d], vt[d]);
    }

    float part = 0.f;
    #pragma unroll
    for (int d = NCOND; d < Dn; d++) {
        float e = vt[d] - ut[d];
        part = fmaf(e, e, part);
    }

    sred[tid] = part;
    __syncthreads();
    // deterministic tree reduction
    for (int s = 64; s > 0; s >>= 1) {
        if (tid < s) sred[tid] += sred[tid + s];
        __syncthreads();
    }
    if (tid == 0) g_partial[bid] = sred[0];
}

// ---------------- final deterministic per-batch sum -----------------------
__global__ void k_finish(float* __restrict__ out) {
    int b = threadIdx.x;
    if (b < Bn) {
        float s = 0.f;
        #pragma unroll
        for (int i = 0; i < 8; i++) s += g_partial[b * 8 + i];
        out[b] = s / (float)(Nn * (Dn - NCOND));
    }
}

// ---------------- launch (graph-capturable, allocation-free) --------------
extern "C" void kernel_launch(void* const* d_in, const int* in_sizes, int n_in,
                              void* d_out, int out_size) {
    const float* data = (const float*)d_in[0];
    const float* c    = (const float*)d_in[1];
    const float* t    = (const float*)d_in[2];
    const float* x0n  = (const float*)d_in[3];
    const float* nb   = (const float*)d_in[4];
    const float* W1   = (const float*)d_in[5];
    const float* Wc   = (const float*)d_in[6];
    const float* Wt   = (const float*)d_in[7];
    const float* b1   = (const float*)d_in[8];
    const float* W2   = (const float*)d_in[9];
    float* out = (float*)d_out;

    k_init<<<(Bn * Nn * Dn + 255) / 256, 256>>>(data, x0n);
    k_cc<<<Bn, Hn>>>(c, Wc);
    k_mismatch<<<Bn * 32, 128>>>(data, 0);
    for (int it = 0; it < MAXIT; it++) {
        k_gate<<<1, 1>>>();
        k_replace<<<(Bn * Nn + 255) / 256, 256>>>(nb, it);
        k_mismatch<<<Bn * 32, 128>>>(data, 1);
    }
    k_final<<<128, 128>>>(data, t, W1, Wt, b1, W2);
    k_finish<<<1, 32>>>(out);
}